// round 3
// baseline (speedup 1.0000x reference)
#include <cuda_runtime.h>
#include <cuda_bf16.h>

#define N_SAMPLES 2048
#define IN_SIZE   256
#define OUT_SIZE  256
#define N_TASKS   128

#define CHUNK     16      // samples per chunk
#define MAXCHUNK  256     // worst-case chunk count (<= 128 + 2048/16)
#define KB        32      // k-tile rows staged per phase
#define CGRP      128     // output cols per block
#define NTHR      128     // threads per block

__device__ int g_off[N_TASKS + 1];
__device__ int g_sidx[N_SAMPLES];
__device__ int g_ctask[MAXCHUNK];
__device__ int g_cstart[MAXCHUNK];
__device__ int g_ccnt[MAXCHUNK];
__device__ int g_nchunks;

// ---------------------------------------------------------------------------
// Kernel 1: group sample indices by task, then build flat chunk list.
// Handles task_ids stored as either int32 or int64 (device-side sniff).
// ---------------------------------------------------------------------------
__global__ void group_kernel(const void* __restrict__ task_ids_raw) {
    __shared__ int cnt[N_TASKS];
    __shared__ int off[N_TASKS + 1];
    __shared__ int hi_or;
    int tid = threadIdx.x;

    const int*       p32 = (const int*)task_ids_raw;
    const long long* p64 = (const long long*)task_ids_raw;

    if (tid == 0) hi_or = 0;
    for (int j = tid; j < N_TASKS; j += blockDim.x) cnt[j] = 0;
    __syncthreads();
    int local_or = 0;
    for (int k = 2 * tid + 1; k < N_SAMPLES; k += 2 * blockDim.x)
        local_or |= p32[k];
    if (local_or) atomicOr(&hi_or, local_or);
    __syncthreads();
    const bool is64 = (hi_or == 0);

    for (int n = tid; n < N_SAMPLES; n += blockDim.x) {
        int t = is64 ? (int)p64[n] : p32[n];
        atomicAdd(&cnt[t], 1);
    }
    __syncthreads();

    if (tid == 0) {
        int s = 0;
        for (int t = 0; t < N_TASKS; t++) { off[t] = s; s += cnt[t]; }
        off[N_TASKS] = s;
        // build chunk list
        int nc = 0;
        for (int t = 0; t < N_TASKS; t++) {
            int n_t = cnt[t];
            for (int b = 0; b < n_t; b += CHUNK) {
                g_ctask[nc]  = t;
                g_cstart[nc] = off[t] + b;
                g_ccnt[nc]   = min(CHUNK, n_t - b);
                nc++;
            }
        }
        g_nchunks = nc;
    }
    __syncthreads();

    for (int j = tid; j <= N_TASKS; j += blockDim.x) g_off[j] = off[j];
    for (int j = tid; j < N_TASKS; j += blockDim.x) cnt[j] = off[j]; // cursor
    __syncthreads();

    for (int n = tid; n < N_SAMPLES; n += blockDim.x) {
        int t = is64 ? (int)p64[n] : p32[n];
        int pos = atomicAdd(&cnt[t], 1);
        g_sidx[pos] = n;
    }
}

// ---------------------------------------------------------------------------
__device__ __forceinline__ void fma2(unsigned long long& acc,
                                     unsigned long long xy,
                                     unsigned long long ww) {
    asm("fma.rn.f32x2 %0, %1, %2, %0;" : "+l"(acc) : "l"(xy), "l"(ww));
}
__device__ __forceinline__ void unpack2(unsigned long long v, float& lo, float& hi) {
    asm("mov.b64 {%0, %1}, %2;" : "=f"(lo), "=f"(hi) : "l"(v));
}

// ---------------------------------------------------------------------------
// Kernel 2: block = (chunk m, col-group g). Tile: 16 samples x 128 cols, K=256.
// Thread (q = tid>>2: col quad, sq = tid&3: sample quad) -> 4 samples x 4 cols.
// W staged in smem k-tiles (coalesced); x staged duplicated as (x,x) pairs so
// both fma.f32x2 operands come straight from LDS.128 with zero packing ops.
// ---------------------------------------------------------------------------
__global__ __launch_bounds__(NTHR, 4)
void tsl_kernel(const float* __restrict__ x,
                const float* __restrict__ W,
                float* __restrict__ out) {
    __shared__ __align__(16) float  wsm[KB * CGRP];            // 16 KB [r][c]
    __shared__ __align__(16) float2 xsm[IN_SIZE * CHUNK];      // 32 KB [i][s] dup pairs

    const int m = blockIdx.x;
    if (m >= g_nchunks) return;
    const int gcol  = blockIdx.y;            // 0 or 1
    const int t     = g_ctask[m];
    const int start = g_cstart[m];
    const int cnt   = g_ccnt[m];
    const int tid   = threadIdx.x;

    // ---- stage x chunk, transposed + duplicated: xsm[i*16 + s] = (x,x) ----
    {
        const int s  = tid & 15;
        const int i0 = (tid >> 4) * 32;      // 8 i-blocks of 32
        const int row = (s < cnt) ? g_sidx[start + s] : -1;
        const float4* xr = (const float4*)(x + (size_t)(row < 0 ? 0 : row) * IN_SIZE);
        #pragma unroll
        for (int j = 0; j < 32; j += 4) {
            float4 v = (row >= 0) ? xr[(i0 + j) >> 2]
                                  : make_float4(0.f, 0.f, 0.f, 0.f);
            xsm[(i0 + j + 0) * CHUNK + s] = make_float2(v.x, v.x);
            xsm[(i0 + j + 1) * CHUNK + s] = make_float2(v.y, v.y);
            xsm[(i0 + j + 2) * CHUNK + s] = make_float2(v.z, v.z);
            xsm[(i0 + j + 3) * CHUNK + s] = make_float2(v.w, v.w);
        }
    }

    const int q  = tid >> 2;                 // col quad 0..31
    const int sq = tid & 3;                  // sample quad 0..3

    unsigned long long a00 = 0, a01 = 0, a10 = 0, a11 = 0;
    unsigned long long a20 = 0, a21 = 0, a30 = 0, a31 = 0;

    const float* Wg = W + (size_t)t * IN_SIZE * OUT_SIZE + gcol * CGRP;

    for (int kt = 0; kt < IN_SIZE / KB; kt++) {
        __syncthreads();                     // also guards x staging on kt=0
        // ---- stage W k-tile: KB x 128 floats, coalesced float4 ----
        {
            const float4* src = (const float4*)(Wg + (size_t)(kt * KB) * OUT_SIZE);
            float4*       dst = (float4*)wsm;
            #pragma unroll
            for (int f = 0; f < (KB * CGRP / 4) / NTHR; f++) {  // 8
                int idx = f * NTHR + tid;                        // float4 index
                int r   = idx >> 5;                              // /32 quads per row
                int c4  = idx & 31;
                dst[idx] = src[(size_t)r * (OUT_SIZE / 4) + c4];
            }
        }
        __syncthreads();

        #pragma unroll 4
        for (int i = 0; i < KB; i++) {
            const ulonglong2* wp = (const ulonglong2*)(wsm + i * CGRP);
            ulonglong2 w2 = wp[q];           // cols q*4..q*4+3 as two f32x2
            const ulonglong2* xp =
                (const ulonglong2*)(xsm + (kt * KB + i) * CHUNK);
            ulonglong2 xa = xp[sq * 2];      // samples 4sq, 4sq+1 (dup pairs)
            ulonglong2 xb = xp[sq * 2 + 1];  // samples 4sq+2, 4sq+3
            fma2(a00, xa.x, w2.x);  fma2(a01, xa.x, w2.y);
            fma2(a10, xa.y, w2.x);  fma2(a11, xa.y, w2.y);
            fma2(a20, xb.x, w2.x);  fma2(a21, xb.x, w2.y);
            fma2(a30, xb.y, w2.x);  fma2(a31, xb.y, w2.y);
        }
    }

    // ---- epilogue: 4 samples x 4 cols per thread, STG.128 per sample ----
    unsigned long long accs[4][2] = {{a00, a01}, {a10, a11}, {a20, a21}, {a30, a31}};
    const int obase = gcol * CGRP + q * 4;
    #pragma unroll
    for (int s = 0; s < 4; s++) {
        int sidx = sq * 4 + s;
        if (sidx < cnt) {
            int row = g_sidx[start + sidx];
            float4 o;
            unpack2(accs[s][0], o.x, o.y);
            unpack2(accs[s][1], o.z, o.w);
            *(float4*)(out + (size_t)row * OUT_SIZE + obase) = o;
        }
    }
}

// ---------------------------------------------------------------------------
extern "C" void kernel_launch(void* const* d_in, const int* in_sizes, int n_in,
                              void* d_out, int out_size) {
    const float* x   = nullptr;
    const void*  tsk = nullptr;
    const float* W   = nullptr;
    for (int i = 0; i < n_in; i++) {
        if (in_sizes[i] == N_SAMPLES * IN_SIZE)               x   = (const float*)d_in[i];
        else if (in_sizes[i] == N_SAMPLES)                    tsk = d_in[i];
        else if (in_sizes[i] == N_TASKS * IN_SIZE * OUT_SIZE) W   = (const float*)d_in[i];
    }
    float* out = (float*)d_out;

    group_kernel<<<1, 256>>>(tsk);
    tsl_kernel<<<dim3(MAXCHUNK, OUT_SIZE / CGRP), NTHR>>>(x, W, out);
}

// round 4
// speedup vs baseline: 1.0611x; 1.0611x over previous
#include <cuda_runtime.h>
#include <cuda_bf16.h>
#include <cstdint>

#define N_SAMPLES 2048
#define IN_SIZE   256
#define OUT_SIZE  256
#define N_TASKS   128

#define CHUNK     16      // samples per chunk
#define MAXCHUNK  256     // worst-case chunk count
#define KHALF     128     // k per block (split-K = 2)
#define NTILE     16      // W rows staged per tile
#define NT        (KHALF / NTILE)   // 8 tiles per half
#define XPAD      20      // xsm row stride in floats (16B-aligned, conflict-lean)

__device__ int g_off[N_TASKS + 1];
__device__ int g_sidx[N_SAMPLES];
__device__ int g_ctask[MAXCHUNK];
__device__ int g_cstart[MAXCHUNK];
__device__ int g_ccnt[MAXCHUNK];
__device__ int g_nchunks;

// ---------------------------------------------------------------------------
// Kernel 1: group sample indices by task, build flat chunk list.
// Handles task_ids stored as either int32 or int64 (device-side sniff).
// ---------------------------------------------------------------------------
__global__ void group_kernel(const void* __restrict__ task_ids_raw) {
    __shared__ int cnt[N_TASKS];
    __shared__ int off[N_TASKS + 1];
    __shared__ int hi_or;
    int tid = threadIdx.x;

    const int*       p32 = (const int*)task_ids_raw;
    const long long* p64 = (const long long*)task_ids_raw;

    if (tid == 0) hi_or = 0;
    for (int j = tid; j < N_TASKS; j += blockDim.x) cnt[j] = 0;
    __syncthreads();
    int local_or = 0;
    for (int k = 2 * tid + 1; k < N_SAMPLES; k += 2 * blockDim.x)
        local_or |= p32[k];
    if (local_or) atomicOr(&hi_or, local_or);
    __syncthreads();
    const bool is64 = (hi_or == 0);

    for (int n = tid; n < N_SAMPLES; n += blockDim.x) {
        int t = is64 ? (int)p64[n] : p32[n];
        atomicAdd(&cnt[t], 1);
    }
    __syncthreads();

    if (tid == 0) {
        int s = 0;
        for (int t = 0; t < N_TASKS; t++) { off[t] = s; s += cnt[t]; }
        off[N_TASKS] = s;
        int nc = 0;
        for (int t = 0; t < N_TASKS; t++) {
            int n_t = cnt[t];
            for (int b = 0; b < n_t; b += CHUNK) {
                g_ctask[nc]  = t;
                g_cstart[nc] = off[t] + b;
                g_ccnt[nc]   = min(CHUNK, n_t - b);
                nc++;
            }
        }
        g_nchunks = nc;
    }
    __syncthreads();

    for (int j = tid; j <= N_TASKS; j += blockDim.x) g_off[j] = off[j];
    for (int j = tid; j < N_TASKS; j += blockDim.x) cnt[j] = off[j]; // cursor
    __syncthreads();

    for (int n = tid; n < N_SAMPLES; n += blockDim.x) {
        int t = is64 ? (int)p64[n] : p32[n];
        int pos = atomicAdd(&cnt[t], 1);
        g_sidx[pos] = n;
    }
}

// ---------------------------------------------------------------------------
__device__ __forceinline__ void fma2(unsigned long long& acc,
                                     unsigned long long xy,
                                     unsigned long long ww) {
    asm("fma.rn.f32x2 %0, %1, %2, %0;" : "+l"(acc) : "l"(xy), "l"(ww));
}
__device__ __forceinline__ unsigned long long pack2(float v) {
    unsigned long long r;
    asm("mov.b64 %0, {%1, %1};" : "=l"(r) : "f"(v));
    return r;
}
__device__ __forceinline__ void unpack2(unsigned long long v, float& lo, float& hi) {
    asm("mov.b64 {%0, %1}, %2;" : "=f"(lo), "=f"(hi) : "l"(v));
}
__device__ __forceinline__ void cp16(uint32_t saddr, const void* g) {
    asm volatile("cp.async.cg.shared.global [%0], [%1], 16;"
                 :: "r"(saddr), "l"(g));
}

// ---------------------------------------------------------------------------
// Kernel 2: block = (chunk m, k-half z). Tile: 16 samples x 256 cols x 128 k.
// 128 threads; thread (q=tid>>2: 8 cols 8q..8q+7, sq=tid&3: samples 4sq..4sq+3)
// -> 32 outputs as 16 f32x2 accumulators.
// W double-buffered through smem via cp.async; x staged plain (duplication
// done in registers on the ALU pipe to halve smem crossbar traffic).
// Both k-halves atomicAdd into zeroed out (2 commutative adds -> deterministic).
// ---------------------------------------------------------------------------
__global__ __launch_bounds__(128)
void tsl_kernel(const float* __restrict__ x,
                const float* __restrict__ W,
                float* __restrict__ out) {
    __shared__ __align__(16) float wsm[2][NTILE * OUT_SIZE];  // 2 x 16 KB
    __shared__ __align__(16) float xsm[KHALF * XPAD];         // 10 KB
    __shared__ int rows_sm[CHUNK];

    const int m = blockIdx.x;
    if (m >= g_nchunks) return;
    const int z     = blockIdx.y;                 // k-half 0/1
    const int t     = g_ctask[m];
    const int start = g_cstart[m];
    const int cnt   = g_ccnt[m];
    const int tid   = threadIdx.x;

    if (tid < CHUNK)
        rows_sm[tid] = (tid < cnt) ? g_sidx[start + tid] : -1;
    __syncthreads();

    // ---- stage x half-chunk, transposed: xsm[i*XPAD + s], i = tid ----
    {
        const float* xi = x + (size_t)z * KHALF + tid;
        #pragma unroll
        for (int s = 0; s < CHUNK; s++) {
            int r = rows_sm[s];
            xsm[tid * XPAD + s] = (r >= 0) ? xi[(size_t)r * IN_SIZE] : 0.0f;
        }
    }

    // ---- W tile prefetch machinery (cp.async, 8 x 16B per thread) ----
    const float* Wt = W + (size_t)t * IN_SIZE * OUT_SIZE
                        + (size_t)z * KHALF * OUT_SIZE;
    uint32_t wsm_sa[2];
    wsm_sa[0] = (uint32_t)__cvta_generic_to_shared(&wsm[0][0]) + tid * 16;
    wsm_sa[1] = (uint32_t)__cvta_generic_to_shared(&wsm[1][0]) + tid * 16;

    #define PREFETCH(kt, b)                                                  \
        {                                                                    \
            const float4* src = (const float4*)(Wt + (kt) * NTILE * OUT_SIZE) \
                                + tid;                                       \
            uint32_t dst = wsm_sa[b];                                        \
            _Pragma("unroll")                                                \
            for (int f = 0; f < (NTILE * OUT_SIZE / 4) / 128; f++)           \
                cp16(dst + f * 128 * 16, src + f * 128);                     \
            asm volatile("cp.async.commit_group;");                          \
        }

    PREFETCH(0, 0);
    PREFETCH(1, 1);

    const int q  = tid >> 2;       // col group: cols 8q..8q+7
    const int sq = tid & 3;        // sample group: samples 4sq..4sq+3

    unsigned long long acc[4][4];
    #pragma unroll
    for (int s = 0; s < 4; s++)
        #pragma unroll
        for (int c = 0; c < 4; c++) acc[s][c] = 0ull;

    for (int kt = 0; kt < NT; kt++) {
        if (kt < NT - 1) asm volatile("cp.async.wait_group 1;");
        else             asm volatile("cp.async.wait_group 0;");
        __syncthreads();

        const float* wb = wsm[kt & 1];
        #pragma unroll 2
        for (int ii = 0; ii < NTILE; ii++) {
            const ulonglong2* wp =
                (const ulonglong2*)(wb + ii * OUT_SIZE + q * 8);
            ulonglong2 wA = wp[0];                 // cols 8q..8q+3
            ulonglong2 wB = wp[1];                 // cols 8q+4..8q+7
            float4 xv = *(const float4*)(xsm + (kt * NTILE + ii) * XPAD + sq * 4);
            unsigned long long x0 = pack2(xv.x);
            unsigned long long x1 = pack2(xv.y);
            unsigned long long x2 = pack2(xv.z);
            unsigned long long x3 = pack2(xv.w);
            fma2(acc[0][0], x0, wA.x); fma2(acc[0][1], x0, wA.y);
            fma2(acc[0][2], x0, wB.x); fma2(acc[0][3], x0, wB.y);
            fma2(acc[1][0], x1, wA.x); fma2(acc[1][1], x1, wA.y);
            fma2(acc[1][2], x1, wB.x); fma2(acc[1][3], x1, wB.y);
            fma2(acc[2][0], x2, wA.x); fma2(acc[2][1], x2, wA.y);
            fma2(acc[2][2], x2, wB.x); fma2(acc[2][3], x2, wB.y);
            fma2(acc[3][0], x3, wA.x); fma2(acc[3][1], x3, wA.y);
            fma2(acc[3][2], x3, wB.x); fma2(acc[3][3], x3, wB.y);
        }
        __syncthreads();
        if (kt + 2 < NT) PREFETCH(kt + 2, kt & 1);
    }

    // ---- epilogue: atomicAdd partial (this k-half) into out ----
    #pragma unroll
    for (int s = 0; s < 4; s++) {
        int sid = sq * 4 + s;
        if (sid < cnt) {
            float* o = out + (size_t)rows_sm[sid] * OUT_SIZE + q * 8;
            #pragma unroll
            for (int c = 0; c < 4; c++) {
                float lo, hi;
                unpack2(acc[s][c], lo, hi);
                atomicAdd(o + 2 * c,     lo);
                atomicAdd(o + 2 * c + 1, hi);
            }
        }
    }
    #undef PREFETCH
}

// ---------------------------------------------------------------------------
extern "C" void kernel_launch(void* const* d_in, const int* in_sizes, int n_in,
                              void* d_out, int out_size) {
    const float* x   = nullptr;
    const void*  tsk = nullptr;
    const float* W   = nullptr;
    for (int i = 0; i < n_in; i++) {
        if (in_sizes[i] == N_SAMPLES * IN_SIZE)               x   = (const float*)d_in[i];
        else if (in_sizes[i] == N_SAMPLES)                    tsk = d_in[i];
        else if (in_sizes[i] == N_TASKS * IN_SIZE * OUT_SIZE) W   = (const float*)d_in[i];
    }
    float* out = (float*)d_out;

    cudaMemsetAsync(out, 0, (size_t)out_size * sizeof(float), 0);
    group_kernel<<<1, 256>>>(tsk);
    tsl_kernel<<<dim3(MAXCHUNK, 2), 128>>>(x, W, out);
}

// round 12
// speedup vs baseline: 1.1067x; 1.0430x over previous
#include <cuda_runtime.h>
#include <cuda_bf16.h>
#include <cstdint>

#define N_SAMPLES 2048
#define IN_SIZE   256
#define OUT_SIZE  256
#define N_TASKS   128

#define CHUNK     16      // samples per chunk
#define MAXCHUNK  256     // worst-case chunk count
#define KHALF     128     // k per block (split-K = 2)
#define NTILE     16      // W rows staged per tile
#define NT        (KHALF / NTILE)   // 8 tiles per half
#define XPAD      20      // xsm row stride in floats (16B-aligned)
#define NTHR      256     // threads per block (8 warps)

__device__ int g_off[N_TASKS + 1];
__device__ int g_sidx[N_SAMPLES];
__device__ int g_ctask[MAXCHUNK];
__device__ int g_cstart[MAXCHUNK];
__device__ int g_ccnt[MAXCHUNK];
__device__ int g_nchunks;

// ---------------------------------------------------------------------------
// Kernel 1: group sample indices by task, build flat chunk list.
// (R4's proven version: serial tid==0 scan, no divergent barriers.)
// Handles task_ids stored as either int32 or int64 (device-side sniff).
// ---------------------------------------------------------------------------
__global__ void group_kernel(const void* __restrict__ task_ids_raw) {
    __shared__ int cnt[N_TASKS];
    __shared__ int off[N_TASKS + 1];
    __shared__ int hi_or;
    int tid = threadIdx.x;

    const int*       p32 = (const int*)task_ids_raw;
    const long long* p64 = (const long long*)task_ids_raw;

    if (tid == 0) hi_or = 0;
    for (int j = tid; j < N_TASKS; j += blockDim.x) cnt[j] = 0;
    __syncthreads();
    int local_or = 0;
    for (int k = 2 * tid + 1; k < N_SAMPLES; k += 2 * blockDim.x)
        local_or |= p32[k];
    if (local_or) atomicOr(&hi_or, local_or);
    __syncthreads();
    const bool is64 = (hi_or == 0);

    for (int n = tid; n < N_SAMPLES; n += blockDim.x) {
        int t = is64 ? (int)p64[n] : p32[n];
        atomicAdd(&cnt[t], 1);
    }
    __syncthreads();

    if (tid == 0) {
        int s = 0;
        for (int t = 0; t < N_TASKS; t++) { off[t] = s; s += cnt[t]; }
        off[N_TASKS] = s;
        int nc = 0;
        for (int t = 0; t < N_TASKS; t++) {
            int n_t = cnt[t];
            for (int b = 0; b < n_t; b += CHUNK) {
                g_ctask[nc]  = t;
                g_cstart[nc] = off[t] + b;
                g_ccnt[nc]   = min(CHUNK, n_t - b);
                nc++;
            }
        }
        g_nchunks = nc;
    }
    __syncthreads();

    for (int j = tid; j <= N_TASKS; j += blockDim.x) g_off[j] = off[j];
    for (int j = tid; j < N_TASKS; j += blockDim.x) cnt[j] = off[j]; // cursor
    __syncthreads();

    for (int n = tid; n < N_SAMPLES; n += blockDim.x) {
        int t = is64 ? (int)p64[n] : p32[n];
        int pos = atomicAdd(&cnt[t], 1);
        g_sidx[pos] = n;
    }
}

// ---------------------------------------------------------------------------
__device__ __forceinline__ void fma2(unsigned long long& acc,
                                     unsigned long long xy,
                                     unsigned long long ww) {
    asm("fma.rn.f32x2 %0, %1, %2, %0;" : "+l"(acc) : "l"(xy), "l"(ww));
}
__device__ __forceinline__ unsigned long long pack2(float v) {
    unsigned long long r;
    asm("mov.b64 %0, {%1, %1};" : "=l"(r) : "f"(v));
    return r;
}
__device__ __forceinline__ void unpack2(unsigned long long v, float& lo, float& hi) {
    asm("mov.b64 {%0, %1}, %2;" : "=f"(lo), "=f"(hi) : "l"(v));
}
__device__ __forceinline__ void cp16(uint32_t saddr, const void* g) {
    asm volatile("cp.async.cg.shared.global [%0], [%1], 16;"
                 :: "r"(saddr), "l"(g));
}

// ---------------------------------------------------------------------------
// Kernel 2: block = (chunk m, k-half z). Tile: 16 samples x 256 cols x 128 k.
// 256 threads (8 warps): thread (q = tid>>2: cols 4q..4q+3,
// sq = tid&3: samples 4sq..4sq+3) -> 16 outputs as 8 f32x2 accumulators.
// W double-buffered via cp.async (full-width 16KB tiles, linear copy —
// identical machinery to the passing R4 kernel); x staged plain, duplicated
// into f32x2 in registers (ALU pipe, hides under FMA).
// k-halves combine via scalar atomicAdd into zeroed out.
// ---------------------------------------------------------------------------
__global__ __launch_bounds__(NTHR)
void tsl_kernel(const float* __restrict__ x,
                const float* __restrict__ W,
                float* __restrict__ out) {
    __shared__ __align__(16) float wsm[2][NTILE * OUT_SIZE];  // 2 x 16 KB
    __shared__ __align__(16) float xsm[KHALF * XPAD];         // 10 KB
    __shared__ int rows_sm[CHUNK];

    const int m = blockIdx.x;
    if (m >= g_nchunks) return;
    const int z     = blockIdx.y;                 // k-half 0/1
    const int t     = g_ctask[m];
    const int start = g_cstart[m];
    const int cnt   = g_ccnt[m];
    const int tid   = threadIdx.x;

    if (tid < CHUNK)
        rows_sm[tid] = (tid < cnt) ? g_sidx[start + tid] : -1;
    __syncthreads();

    // ---- stage x half-chunk, transposed: xsm[i*XPAD + s], i = tid < 128 ----
    if (tid < KHALF) {
        const float* xi = x + (size_t)z * KHALF + tid;
        #pragma unroll
        for (int s = 0; s < CHUNK; s++) {
            int r = rows_sm[s];
            xsm[tid * XPAD + s] = (r >= 0) ? xi[(size_t)r * IN_SIZE] : 0.0f;
        }
    }

    // ---- W tile prefetch (cp.async): tile = 16 rows x 256 cols = 16 KB ----
    const float* Wt = W + (size_t)t * IN_SIZE * OUT_SIZE
                        + (size_t)z * KHALF * OUT_SIZE;
    uint32_t wsa[2];
    wsa[0] = (uint32_t)__cvta_generic_to_shared(&wsm[0][0]);
    wsa[1] = (uint32_t)__cvta_generic_to_shared(&wsm[1][0]);

    #define PREFETCH(kt, b)                                                   \
        {                                                                     \
            const float4* src = (const float4*)(Wt + (kt) * NTILE * OUT_SIZE);\
            _Pragma("unroll")                                                 \
            for (int f = 0; f < (NTILE * OUT_SIZE / 4) / NTHR; f++) {         \
                int idx = f * NTHR + tid;                                     \
                cp16(wsa[b] + idx * 16, src + idx);                           \
            }                                                                 \
            asm volatile("cp.async.commit_group;");                           \
        }

    PREFETCH(0, 0);
    PREFETCH(1, 1);

    const int q  = tid >> 2;       // cols 4q..4q+3  (0..63)
    const int sq = tid & 3;        // samples 4sq..4sq+3

    unsigned long long acc[4][2];
    #pragma unroll
    for (int s = 0; s < 4; s++) { acc[s][0] = 0ull; acc[s][1] = 0ull; }

    for (int kt = 0; kt < NT; kt++) {
        if (kt < NT - 1) asm volatile("cp.async.wait_group 1;");
        else             asm volatile("cp.async.wait_group 0;");
        __syncthreads();

        const float* wb = wsm[kt & 1];
        #pragma unroll 4
        for (int ii = 0; ii < NTILE; ii++) {
            ulonglong2 w2 = *(const ulonglong2*)(wb + ii * OUT_SIZE + q * 4);
            float4 xv = *(const float4*)(xsm + (kt * NTILE + ii) * XPAD + sq * 4);
            unsigned long long x0 = pack2(xv.x);
            unsigned long long x1 = pack2(xv.y);
            unsigned long long x2 = pack2(xv.z);
            unsigned long long x3 = pack2(xv.w);
            fma2(acc[0][0], x0, w2.x); fma2(acc[0][1], x0, w2.y);
            fma2(acc[1][0], x1, w2.x); fma2(acc[1][1], x1, w2.y);
            fma2(acc[2][0], x2, w2.x); fma2(acc[2][1], x2, w2.y);
            fma2(acc[3][0], x3, w2.x); fma2(acc[3][1], x3, w2.y);
        }
        __syncthreads();
        if (kt + 2 < NT) PREFETCH(kt + 2, kt & 1);
    }

    // ---- epilogue: scalar atomicAdd partials into zeroed out ----
    #pragma unroll
    for (int s = 0; s < 4; s++) {
        int sid = sq * 4 + s;
        if (sid < cnt) {
            float* o = out + (size_t)rows_sm[sid] * OUT_SIZE + q * 4;
            float f0, f1, f2, f3;
            unpack2(acc[s][0], f0, f1);
            unpack2(acc[s][1], f2, f3);
            atomicAdd(o + 0, f0);
            atomicAdd(o + 1, f1);
            atomicAdd(o + 2, f2);
            atomicAdd(o + 3, f3);
        }
    }
    #undef PREFETCH
}

// ---------------------------------------------------------------------------
extern "C" void kernel_launch(void* const* d_in, const int* in_sizes, int n_in,
                              void* d_out, int out_size) {
    const float* x   = nullptr;
    const void*  tsk = nullptr;
    const float* W   = nullptr;
    for (int i = 0; i < n_in; i++) {
        if (in_sizes[i] == N_SAMPLES * IN_SIZE)               x   = (const float*)d_in[i];
        else if (in_sizes[i] == N_SAMPLES)                    tsk = d_in[i];
        else if (in_sizes[i] == N_TASKS * IN_SIZE * OUT_SIZE) W   = (const float*)d_in[i];
    }
    float* out = (float*)d_out;

    cudaMemsetAsync(out, 0, (size_t)out_size * sizeof(float), 0);
    group_kernel<<<1, 256>>>(tsk);
    tsl_kernel<<<dim3(MAXCHUNK, 2), NTHR>>>(x, W, out);
}

// round 14
// speedup vs baseline: 1.2346x; 1.1156x over previous
#include <cuda_runtime.h>
#include <cuda_bf16.h>
#include <cstdint>

#define N_SAMPLES 2048
#define IN_SIZE   256
#define OUT_SIZE  256
#define N_TASKS   128

#define CHUNK     16      // samples per chunk
#define MAXCHUNK  256     // worst-case chunk count
#define KHALF     128     // k per block (split-K = 2)
#define CGRP      128     // cols per block (col-split = 2)
#define NTILE     32      // W rows staged per tile
#define NT        (KHALF / NTILE)   // 4 tiles per half
#define XPAD      20      // xsm row stride in floats (16B-aligned)
#define NTHR      128     // threads per block (4 warps)

__device__ int g_off[N_TASKS + 1];
__device__ int g_sidx[N_SAMPLES];
__device__ int g_ctask[MAXCHUNK];
__device__ int g_cstart[MAXCHUNK];
__device__ int g_ccnt[MAXCHUNK];
__device__ int g_nchunks;

// ---------------------------------------------------------------------------
// Kernel 1: group sample indices by task, build flat chunk list.
// (Proven R4/R12 version: serial tid==0 scan, no divergent barriers.)
// Handles task_ids stored as either int32 or int64 (device-side sniff).
// ---------------------------------------------------------------------------
__global__ void group_kernel(const void* __restrict__ task_ids_raw) {
    __shared__ int cnt[N_TASKS];
    __shared__ int off[N_TASKS + 1];
    __shared__ int hi_or;
    int tid = threadIdx.x;

    const int*       p32 = (const int*)task_ids_raw;
    const long long* p64 = (const long long*)task_ids_raw;

    if (tid == 0) hi_or = 0;
    for (int j = tid; j < N_TASKS; j += blockDim.x) cnt[j] = 0;
    __syncthreads();
    int local_or = 0;
    for (int k = 2 * tid + 1; k < N_SAMPLES; k += 2 * blockDim.x)
        local_or |= p32[k];
    if (local_or) atomicOr(&hi_or, local_or);
    __syncthreads();
    const bool is64 = (hi_or == 0);

    for (int n = tid; n < N_SAMPLES; n += blockDim.x) {
        int t = is64 ? (int)p64[n] : p32[n];
        atomicAdd(&cnt[t], 1);
    }
    __syncthreads();

    if (tid == 0) {
        int s = 0;
        for (int t = 0; t < N_TASKS; t++) { off[t] = s; s += cnt[t]; }
        off[N_TASKS] = s;
        int nc = 0;
        for (int t = 0; t < N_TASKS; t++) {
            int n_t = cnt[t];
            for (int b = 0; b < n_t; b += CHUNK) {
                g_ctask[nc]  = t;
                g_cstart[nc] = off[t] + b;
                g_ccnt[nc]   = min(CHUNK, n_t - b);
                nc++;
            }
        }
        g_nchunks = nc;
    }
    __syncthreads();

    for (int j = tid; j <= N_TASKS; j += blockDim.x) g_off[j] = off[j];
    for (int j = tid; j < N_TASKS; j += blockDim.x) cnt[j] = off[j]; // cursor
    __syncthreads();

    for (int n = tid; n < N_SAMPLES; n += blockDim.x) {
        int t = is64 ? (int)p64[n] : p32[n];
        int pos = atomicAdd(&cnt[t], 1);
        g_sidx[pos] = n;
    }
}

// ---------------------------------------------------------------------------
__device__ __forceinline__ void fma2(unsigned long long& acc,
                                     unsigned long long xy,
                                     unsigned long long ww) {
    asm("fma.rn.f32x2 %0, %1, %2, %0;" : "+l"(acc) : "l"(xy), "l"(ww));
}
__device__ __forceinline__ unsigned long long pack2(float v) {
    unsigned long long r;
    asm("mov.b64 %0, {%1, %1};" : "=l"(r) : "f"(v));
    return r;
}
__device__ __forceinline__ void unpack2(unsigned long long v, float& lo, float& hi) {
    asm("mov.b64 {%0, %1}, %2;" : "=f"(lo), "=f"(hi) : "l"(v));
}
__device__ __forceinline__ void cp16(uint32_t saddr, const void* g) {
    asm volatile("cp.async.cg.shared.global [%0], [%1], 16;"
                 :: "r"(saddr), "l"(g));
}
__device__ __forceinline__ void red4(float* p, float a, float b, float c, float d) {
    asm volatile("red.global.add.v4.f32 [%0], {%1, %2, %3, %4};"
                 :: "l"(p), "f"(a), "f"(b), "f"(c), "f"(d) : "memory");
}

// ---------------------------------------------------------------------------
// Kernel 2: block = (chunk m, col-half gcol, k-half z).
// Tile: 16 samples x 128 cols x 128 k. 128 threads (4 warps).
// Thread map (FIXED from R9): q = tid>>2 in [0,32) -> cols 4q..4q+3 (covers
// exactly CGRP=128); sq = tid&3 -> samples 4sq..4sq+3. 8 f32x2 accumulators.
// W double-buffered via cp.async (32-row, 16KB tiles); x staged plain and
// duplicated into f32x2 in registers (ALU pipe, hides under FMA).
// Halves combine via red.global.add.v4.f32 into zeroed out (16B aligned).
// ---------------------------------------------------------------------------
__global__ __launch_bounds__(NTHR)
void tsl_kernel(const float* __restrict__ x,
                const float* __restrict__ W,
                float* __restrict__ out) {
    __shared__ __align__(16) float wsm[2][NTILE * CGRP];   // 2 x 16 KB
    __shared__ __align__(16) float xsm[KHALF * XPAD];      // 10 KB
    __shared__ int rows_sm[CHUNK];

    const int m = blockIdx.x;
    if (m >= g_nchunks) return;
    const int gcol  = blockIdx.y;                 // col half 0/1
    const int z     = blockIdx.z;                 // k half 0/1
    const int t     = g_ctask[m];
    const int start = g_cstart[m];
    const int cnt   = g_ccnt[m];
    const int tid   = threadIdx.x;

    if (tid < CHUNK)
        rows_sm[tid] = (tid < cnt) ? g_sidx[start + tid] : -1;
    __syncthreads();

    // ---- stage x half-chunk, transposed: xsm[i*XPAD + s], i = tid ----
    {
        const float* xi = x + (size_t)z * KHALF + tid;
        #pragma unroll
        for (int s = 0; s < CHUNK; s++) {
            int r = rows_sm[s];
            xsm[tid * XPAD + s] = (r >= 0) ? xi[(size_t)r * IN_SIZE] : 0.0f;
        }
    }

    // ---- W prefetch (cp.async): tile = 32 rows x 128 cols = 16 KB ----
    const float* Wt = W + (size_t)t * IN_SIZE * OUT_SIZE
                        + (size_t)z * KHALF * OUT_SIZE + gcol * CGRP;
    uint32_t wsa[2];
    wsa[0] = (uint32_t)__cvta_generic_to_shared(&wsm[0][0]);
    wsa[1] = (uint32_t)__cvta_generic_to_shared(&wsm[1][0]);

    #define PREFETCH(kt, b)                                                   \
        {                                                                     \
            _Pragma("unroll")                                                 \
            for (int f = 0; f < (NTILE * CGRP / 4) / NTHR; f++) {             \
                int idx = f * NTHR + tid;                                     \
                int r   = idx >> 5;        /* 32 float4 per row */            \
                int c4  = idx & 31;                                           \
                cp16(wsa[b] + idx * 16,                                       \
                     (const float4*)(Wt + (size_t)((kt) * NTILE + r) *        \
                                              OUT_SIZE) + c4);                \
            }                                                                 \
            asm volatile("cp.async.commit_group;");                           \
        }

    PREFETCH(0, 0);
    PREFETCH(1, 1);

    const int q  = tid >> 2;       // cols 4q..4q+3  (q in [0,32) -> 128 cols)
    const int sq = tid & 3;        // samples 4sq..4sq+3

    unsigned long long acc[4][2];
    #pragma unroll
    for (int s = 0; s < 4; s++) { acc[s][0] = 0ull; acc[s][1] = 0ull; }

    for (int kt = 0; kt < NT; kt++) {
        if (kt < NT - 1) asm volatile("cp.async.wait_group 1;");
        else             asm volatile("cp.async.wait_group 0;");
        __syncthreads();

        const float* wb = wsm[kt & 1];
        #pragma unroll 4
        for (int ii = 0; ii < NTILE; ii++) {
            ulonglong2 w2 = *(const ulonglong2*)(wb + ii * CGRP + q * 4);
            float4 xv = *(const float4*)(xsm + (kt * NTILE + ii) * XPAD + sq * 4);
            unsigned long long x0 = pack2(xv.x);
            unsigned long long x1 = pack2(xv.y);
            unsigned long long x2 = pack2(xv.z);
            unsigned long long x3 = pack2(xv.w);
            fma2(acc[0][0], x0, w2.x); fma2(acc[0][1], x0, w2.y);
            fma2(acc[1][0], x1, w2.x); fma2(acc[1][1], x1, w2.y);
            fma2(acc[2][0], x2, w2.x); fma2(acc[2][1], x2, w2.y);
            fma2(acc[3][0], x3, w2.x); fma2(acc[3][1], x3, w2.y);
        }
        __syncthreads();
        if (kt + 2 < NT) PREFETCH(kt + 2, kt & 1);
    }

    // ---- epilogue: one red.global.add.v4 per (sample, thread) ----
    const int obase = gcol * CGRP + q * 4;        // 16B aligned
    #pragma unroll
    for (int s = 0; s < 4; s++) {
        int sid = sq * 4 + s;
        if (sid < cnt) {
            float* o = out + (size_t)rows_sm[sid] * OUT_SIZE + obase;
            float f0, f1, f2, f3;
            unpack2(acc[s][0], f0, f1);
            unpack2(acc[s][1], f2, f3);
            red4(o, f0, f1, f2, f3);
        }
    }
    #undef PREFETCH
}

// ---------------------------------------------------------------------------
extern "C" void kernel_launch(void* const* d_in, const int* in_sizes, int n_in,
                              void* d_out, int out_size) {
    const float* x   = nullptr;
    const void*  tsk = nullptr;
    const float* W   = nullptr;
    for (int i = 0; i < n_in; i++) {
        if (in_sizes[i] == N_SAMPLES * IN_SIZE)               x   = (const float*)d_in[i];
        else if (in_sizes[i] == N_SAMPLES)                    tsk = d_in[i];
        else if (in_sizes[i] == N_TASKS * IN_SIZE * OUT_SIZE) W   = (const float*)d_in[i];
    }
    float* out = (float*)d_out;

    cudaMemsetAsync(out, 0, (size_t)out_size * sizeof(float), 0);
    group_kernel<<<1, 256>>>(tsk);
    tsl_kernel<<<dim3(MAXCHUNK, 2, 2), NTHR>>>(x, W, out);
}

// round 15
// speedup vs baseline: 1.8393x; 1.4898x over previous
#include <cuda_runtime.h>
#include <cuda_bf16.h>
#include <cstdint>

#define N_SAMPLES 2048
#define IN_SIZE   256
#define OUT_SIZE  256
#define N_TASKS   128

#define CHUNK     16      // samples per chunk
#define MAXCHUNK  256     // worst-case chunk count
#define KHALF     128     // k per block (split-K = 2)
#define CGRP      128     // cols per block (col-split = 2)
#define NTILE     16      // W rows staged per tile
#define NT        (KHALF / NTILE)   // 8 tiles per half
#define XPAD      20      // xsm row stride in floats (16B-aligned)
#define NTHR      128     // threads per block (4 warps)

__device__ int g_sidx[N_SAMPLES];
__device__ int g_ctask[MAXCHUNK];
__device__ int g_cstart[MAXCHUNK];
__device__ int g_ccnt[MAXCHUNK];
__device__ int g_nchunks;

// ---------------------------------------------------------------------------
// Kernel 1: group sample indices by task + flat chunk list.
// 128 threads, fully parallel: warp-shuffle scans (all threads of all 4 warps
// execute every barrier — no divergent sync), parallel chunk emit, atomic
// scatter. Handles task_ids as int32 or int64 (device-side sniff).
// ---------------------------------------------------------------------------
__global__ __launch_bounds__(N_TASKS)
void group_kernel(const void* __restrict__ task_ids_raw) {
    __shared__ int cnt[N_TASKS];
    __shared__ int cursor[N_TASKS];
    __shared__ int wsum1[4], wsum2[4];
    __shared__ int hi_or;
    const int tid  = threadIdx.x;      // 0..127, one task per thread
    const int lane = tid & 31;
    const int wid  = tid >> 5;

    const int*       p32 = (const int*)task_ids_raw;
    const long long* p64 = (const long long*)task_ids_raw;

    if (tid == 0) hi_or = 0;
    cnt[tid] = 0;
    __syncthreads();

    int local_or = 0;
    for (int k = 2 * tid + 1; k < N_SAMPLES; k += 2 * N_TASKS)
        local_or |= p32[k];
    if (local_or) atomicOr(&hi_or, local_or);
    __syncthreads();
    const bool is64 = (hi_or == 0);

    for (int n = tid; n < N_SAMPLES; n += N_TASKS) {
        int t = is64 ? (int)p64[n] : p32[n];
        atomicAdd(&cnt[t], 1);
    }
    __syncthreads();

    // ---- parallel exclusive scans (samples, chunks) over 128 tasks ----
    const int c  = cnt[tid];
    const int nc = (c + CHUNK - 1) / CHUNK;
    int s1 = c, s2 = nc;                     // inclusive warp scans
    #pragma unroll
    for (int d = 1; d < 32; d <<= 1) {
        int v1 = __shfl_up_sync(0xffffffff, s1, d);
        int v2 = __shfl_up_sync(0xffffffff, s2, d);
        if (lane >= d) { s1 += v1; s2 += v2; }
    }
    if (lane == 31) { wsum1[wid] = s1; wsum2[wid] = s2; }
    __syncthreads();
    int b1 = 0, b2 = 0;
    #pragma unroll
    for (int w = 0; w < 4; w++)
        if (w < wid) { b1 += wsum1[w]; b2 += wsum2[w]; }
    const int soff = b1 + s1 - c;            // exclusive sample offset
    const int coff = b2 + s2 - nc;           // exclusive chunk offset
    if (tid == N_TASKS - 1) g_nchunks = b2 + s2;

    // ---- parallel chunk emit ----
    for (int b = 0, j = 0; b < c; b += CHUNK, j++) {
        g_ctask[coff + j]  = tid;
        g_cstart[coff + j] = soff + b;
        g_ccnt[coff + j]   = min(CHUNK, c - b);
    }

    cursor[tid] = soff;
    __syncthreads();

    // ---- scatter sample indices ----
    for (int n = tid; n < N_SAMPLES; n += N_TASKS) {
        int t = is64 ? (int)p64[n] : p32[n];
        int pos = atomicAdd(&cursor[t], 1);
        g_sidx[pos] = n;
    }
}

// ---------------------------------------------------------------------------
__device__ __forceinline__ void fma2(unsigned long long& acc,
                                     unsigned long long xy,
                                     unsigned long long ww) {
    asm("fma.rn.f32x2 %0, %1, %2, %0;" : "+l"(acc) : "l"(xy), "l"(ww));
}
__device__ __forceinline__ unsigned long long pack2(float v) {
    unsigned long long r;
    asm("mov.b64 %0, {%1, %1};" : "=l"(r) : "f"(v));
    return r;
}
__device__ __forceinline__ void unpack2(unsigned long long v, float& lo, float& hi) {
    asm("mov.b64 {%0, %1}, %2;" : "=f"(lo), "=f"(hi) : "l"(v));
}
__device__ __forceinline__ void cp16(uint32_t saddr, const void* g) {
    asm volatile("cp.async.cg.shared.global [%0], [%1], 16;"
                 :: "r"(saddr), "l"(g));
}
__device__ __forceinline__ void red4(float* p, float a, float b, float c, float d) {
    asm volatile("red.global.add.v4.f32 [%0], {%1, %2, %3, %4};"
                 :: "l"(p), "f"(a), "f"(b), "f"(c), "f"(d) : "memory");
}

// ---------------------------------------------------------------------------
// Kernel 2: block = (chunk m, col-half gcol, k-half z).
// Tile: 16 samples x 128 cols x 128 k. 128 threads (4 warps).
// q = tid>>2 in [0,32) -> cols 4q..4q+3; sq = tid&3 -> samples 4sq..4sq+3.
// 8 f32x2 accumulators. W double-buffered via cp.async (16-row, 8KB tiles;
// smem 26.5KB -> ~7 blocks/SM resident). Halves combine via red.global.add.v4.
// ---------------------------------------------------------------------------
__global__ __launch_bounds__(NTHR, 7)
void tsl_kernel(const float* __restrict__ x,
                const float* __restrict__ W,
                float* __restrict__ out) {
    __shared__ __align__(16) float wsm[2][NTILE * CGRP];   // 2 x 8 KB
    __shared__ __align__(16) float xsm[KHALF * XPAD];      // 10 KB
    __shared__ int rows_sm[CHUNK];

    const int m = blockIdx.x;
    if (m >= g_nchunks) return;
    const int gcol  = blockIdx.y;                 // col half 0/1
    const int z     = blockIdx.z;                 // k half 0/1
    const int t     = g_ctask[m];
    const int start = g_cstart[m];
    const int cnt   = g_ccnt[m];
    const int tid   = threadIdx.x;

    if (tid < CHUNK)
        rows_sm[tid] = (tid < cnt) ? g_sidx[start + tid] : -1;
    __syncthreads();

    // ---- stage x half-chunk, transposed: xsm[i*XPAD + s], i = tid ----
    {
        const float* xi = x + (size_t)z * KHALF + tid;
        #pragma unroll
        for (int s = 0; s < CHUNK; s++) {
            int r = rows_sm[s];
            xsm[tid * XPAD + s] = (r >= 0) ? xi[(size_t)r * IN_SIZE] : 0.0f;
        }
    }

    // ---- W prefetch (cp.async): tile = 16 rows x 128 cols = 8 KB ----
    const float* Wt = W + (size_t)t * IN_SIZE * OUT_SIZE
                        + (size_t)z * KHALF * OUT_SIZE + gcol * CGRP;
    uint32_t wsa[2];
    wsa[0] = (uint32_t)__cvta_generic_to_shared(&wsm[0][0]);
    wsa[1] = (uint32_t)__cvta_generic_to_shared(&wsm[1][0]);

    #define PREFETCH(kt, b)                                                   \
        {                                                                     \
            _Pragma("unroll")                                                 \
            for (int f = 0; f < (NTILE * CGRP / 4) / NTHR; f++) {             \
                int idx = f * NTHR + tid;                                     \
                int r   = idx >> 5;        /* 32 float4 per row */            \
                int c4  = idx & 31;                                           \
                cp16(wsa[b] + idx * 16,                                       \
                     (const float4*)(Wt + (size_t)((kt) * NTILE + r) *        \
                                              OUT_SIZE) + c4);                \
            }                                                                 \
            asm volatile("cp.async.commit_group;");                           \
        }

    PREFETCH(0, 0);
    PREFETCH(1, 1);

    const int q  = tid >> 2;       // cols 4q..4q+3
    const int sq = tid & 3;        // samples 4sq..4sq+3

    unsigned long long acc[4][2];
    #pragma unroll
    for (int s = 0; s < 4; s++) { acc[s][0] = 0ull; acc[s][1] = 0ull; }

    for (int kt = 0; kt < NT; kt++) {
        if (kt < NT - 1) asm volatile("cp.async.wait_group 1;");
        else             asm volatile("cp.async.wait_group 0;");
        __syncthreads();

        const float* wb = wsm[kt & 1];
        #pragma unroll 4
        for (int ii = 0; ii < NTILE; ii++) {
            ulonglong2 w2 = *(const ulonglong2*)(wb + ii * CGRP + q * 4);
            float4 xv = *(const float4*)(xsm + (kt * NTILE + ii) * XPAD + sq * 4);
            unsigned long long x0 = pack2(xv.x);
            unsigned long long x1 = pack2(xv.y);
            unsigned long long x2 = pack2(xv.z);
            unsigned long long x3 = pack2(xv.w);
            fma2(acc[0][0], x0, w2.x); fma2(acc[0][1], x0, w2.y);
            fma2(acc[1][0], x1, w2.x); fma2(acc[1][1], x1, w2.y);
            fma2(acc[2][0], x2, w2.x); fma2(acc[2][1], x2, w2.y);
            fma2(acc[3][0], x3, w2.x); fma2(acc[3][1], x3, w2.y);
        }
        __syncthreads();
        if (kt + 2 < NT) PREFETCH(kt + 2, kt & 1);
    }

    // ---- epilogue: one red.global.add.v4 per (sample, thread) ----
    const int obase = gcol * CGRP + q * 4;        // 16B aligned
    #pragma unroll
    for (int s = 0; s < 4; s++) {
        int sid = sq * 4 + s;
        if (sid < cnt) {
            float* o = out + (size_t)rows_sm[sid] * OUT_SIZE + obase;
            float f0, f1, f2, f3;
            unpack2(acc[s][0], f0, f1);
            unpack2(acc[s][1], f2, f3);
            red4(o, f0, f1, f2, f3);
        }
    }
    #undef PREFETCH
}

// ---------------------------------------------------------------------------
extern "C" void kernel_launch(void* const* d_in, const int* in_sizes, int n_in,
                              void* d_out, int out_size) {
    const float* x   = nullptr;
    const void*  tsk = nullptr;
    const float* W   = nullptr;
    for (int i = 0; i < n_in; i++) {
        if (in_sizes[i] == N_SAMPLES * IN_SIZE)               x   = (const float*)d_in[i];
        else if (in_sizes[i] == N_SAMPLES)                    tsk = d_in[i];
        else if (in_sizes[i] == N_TASKS * IN_SIZE * OUT_SIZE) W   = (const float*)d_in[i];
    }
    float* out = (float*)d_out;

    cudaMemsetAsync(out, 0, (size_t)out_size * sizeof(float), 0);
    group_kernel<<<1, N_TASKS>>>(tsk);
    tsl_kernel<<<dim3(MAXCHUNK, 2, 2), NTHR>>>(x, W, out);
}

// round 16
// speedup vs baseline: 1.8727x; 1.0182x over previous
#include <cuda_runtime.h>
#include <cuda_bf16.h>
#include <cstdint>

#define N_SAMPLES 2048
#define IN_SIZE   256
#define OUT_SIZE  256
#define N_TASKS   128

#define CHUNK     16      // samples per chunk
#define MAXCHUNK  256     // worst-case chunk count
#define KQ        64      // k per block (split-K = 4)
#define NSPLIT    4
#define XPAD      20      // xsm row stride in floats (80B = 5x16B, keeps float4 align)
#define NTHR      128

__device__ int g_sidx[N_SAMPLES];
__device__ int g_ctask[MAXCHUNK];
__device__ int g_cstart[MAXCHUNK];
__device__ int g_ccnt[MAXCHUNK];
__device__ int g_nchunks;

// ---------------------------------------------------------------------------
// Kernel 1: group sample indices by task + flat chunk list (proven R15
// version): 128 threads, warp-shuffle scans, parallel chunk emit, atomic
// scatter. Handles task_ids as int32 or int64 (device-side sniff).
// ---------------------------------------------------------------------------
__global__ __launch_bounds__(N_TASKS)
void group_kernel(const void* __restrict__ task_ids_raw) {
    __shared__ int cnt[N_TASKS];
    __shared__ int cursor[N_TASKS];
    __shared__ int wsum1[4], wsum2[4];
    __shared__ int hi_or;
    const int tid  = threadIdx.x;
    const int lane = tid & 31;
    const int wid  = tid >> 5;

    const int*       p32 = (const int*)task_ids_raw;
    const long long* p64 = (const long long*)task_ids_raw;

    if (tid == 0) hi_or = 0;
    cnt[tid] = 0;
    __syncthreads();

    int local_or = 0;
    for (int k = 2 * tid + 1; k < N_SAMPLES; k += 2 * N_TASKS)
        local_or |= p32[k];
    if (local_or) atomicOr(&hi_or, local_or);
    __syncthreads();
    const bool is64 = (hi_or == 0);

    for (int n = tid; n < N_SAMPLES; n += N_TASKS) {
        int t = is64 ? (int)p64[n] : p32[n];
        atomicAdd(&cnt[t], 1);
    }
    __syncthreads();

    const int c  = cnt[tid];
    const int nc = (c + CHUNK - 1) / CHUNK;
    int s1 = c, s2 = nc;
    #pragma unroll
    for (int d = 1; d < 32; d <<= 1) {
        int v1 = __shfl_up_sync(0xffffffff, s1, d);
        int v2 = __shfl_up_sync(0xffffffff, s2, d);
        if (lane >= d) { s1 += v1; s2 += v2; }
    }
    if (lane == 31) { wsum1[wid] = s1; wsum2[wid] = s2; }
    __syncthreads();
    int b1 = 0, b2 = 0;
    #pragma unroll
    for (int w = 0; w < 4; w++)
        if (w < wid) { b1 += wsum1[w]; b2 += wsum2[w]; }
    const int soff = b1 + s1 - c;
    const int coff = b2 + s2 - nc;
    if (tid == N_TASKS - 1) g_nchunks = b2 + s2;

    for (int b = 0, j = 0; b < c; b += CHUNK, j++) {
        g_ctask[coff + j]  = tid;
        g_cstart[coff + j] = soff + b;
        g_ccnt[coff + j]   = min(CHUNK, c - b);
    }

    cursor[tid] = soff;
    __syncthreads();

    for (int n = tid; n < N_SAMPLES; n += N_TASKS) {
        int t = is64 ? (int)p64[n] : p32[n];
        int pos = atomicAdd(&cursor[t], 1);
        g_sidx[pos] = n;
    }
}

// ---------------------------------------------------------------------------
__device__ __forceinline__ void fma2(unsigned long long& acc,
                                     unsigned long long xy,
                                     unsigned long long ww) {
    asm("fma.rn.f32x2 %0, %1, %2, %0;" : "+l"(acc) : "l"(xy), "l"(ww));
}
__device__ __forceinline__ unsigned long long pack2(float v) {
    unsigned long long r;
    asm("mov.b64 %0, {%1, %1};" : "=l"(r) : "f"(v));
    return r;
}
__device__ __forceinline__ void unpack2(unsigned long long v, float& lo, float& hi) {
    asm("mov.b64 {%0, %1}, %2;" : "=f"(lo), "=f"(hi) : "l"(v));
}
__device__ __forceinline__ void red4(float* p, float a, float b, float c, float d) {
    asm volatile("red.global.add.v4.f32 [%0], {%1, %2, %3, %4};"
                 :: "l"(p), "f"(a), "f"(b), "f"(c), "f"(d) : "memory");
}

// ---------------------------------------------------------------------------
// Kernel 2: block = (chunk m, k-quarter z). Tile: 16 samples x 256 cols x 64 k.
// 128 threads. Thread: sh = tid>>6 -> samples 8sh..8sh+7;
//                      q  = tid&63 -> cols 4q..4q+3.
// W: direct coalesced LDG.128 from L2 with a depth-4 register prefetch ring
//    (never touches the smem crossbar). x: tiny smem tile, read as packed
//    (s,s+1) f32x2 pairs via LDS.128, W pairs come natural from the LDG.
// x is duplicated per-sample via ALU movs (hide under FMA). No mainloop
// barriers -> warps with no valid samples exit early.
// k-quarters combine via red.global.add.v4.f32 into zeroed out.
// ---------------------------------------------------------------------------
__global__ __launch_bounds__(NTHR)
void tsl_kernel(const float* __restrict__ x,
                const float* __restrict__ W,
                float* __restrict__ out) {
    __shared__ __align__(16) float xsm[KQ * XPAD];   // 5.1 KB
    __shared__ int rows_sm[CHUNK];

    const int m = blockIdx.x;
    if (m >= g_nchunks) return;
    const int z     = blockIdx.y;                 // k quarter 0..3
    const int t     = g_ctask[m];
    const int start = g_cstart[m];
    const int cnt   = g_ccnt[m];
    const int tid   = threadIdx.x;

    if (tid < CHUNK)
        rows_sm[tid] = (tid < cnt) ? g_sidx[start + tid] : -1;
    __syncthreads();

    // ---- stage x quarter, transposed: xsm[i*XPAD + s] ----
    // thread: s = tid&15, covers 8 i values starting at (tid>>4)*8
    {
        const int s  = tid & 15;
        const int i0 = (tid >> 4) * 8;
        const int r  = rows_sm[s];
        if (r >= 0) {
            const float4* xr =
                (const float4*)(x + (size_t)r * IN_SIZE + z * KQ + i0);
            float4 a = xr[0], b = xr[1];
            xsm[(i0 + 0) * XPAD + s] = a.x;
            xsm[(i0 + 1) * XPAD + s] = a.y;
            xsm[(i0 + 2) * XPAD + s] = a.z;
            xsm[(i0 + 3) * XPAD + s] = a.w;
            xsm[(i0 + 4) * XPAD + s] = b.x;
            xsm[(i0 + 5) * XPAD + s] = b.y;
            xsm[(i0 + 6) * XPAD + s] = b.z;
            xsm[(i0 + 7) * XPAD + s] = b.w;
        } else {
            #pragma unroll
            for (int j = 0; j < 8; j++) xsm[(i0 + j) * XPAD + s] = 0.0f;
        }
    }
    __syncthreads();

    const int sh = tid >> 6;       // sample half (warp-uniform)
    const int q  = tid & 63;       // col quad: cols 4q..4q+3

    if (sh * 8 < cnt) {
        // W rows for this k-quarter; 16B per thread, coalesced per warp.
        const ulonglong2* wp =
            (const ulonglong2*)(W + (size_t)t * IN_SIZE * OUT_SIZE
                                  + (size_t)z * KQ * OUT_SIZE) + q;
        // depth-4 prefetch ring
        ulonglong2 wreg[4];
        #pragma unroll
        for (int j = 0; j < 4; j++)
            wreg[j] = wp[(size_t)j * (OUT_SIZE / 4)];

        unsigned long long acc[8][2];
        #pragma unroll
        for (int s = 0; s < 8; s++) { acc[s][0] = 0ull; acc[s][1] = 0ull; }

        const float* xb = xsm + sh * 8;
        for (int ib = 0; ib < KQ / 4; ib++) {
            #pragma unroll
            for (int j = 0; j < 4; j++) {
                const int i = ib * 4 + j;
                ulonglong2 w2 = wreg[j];
                int ipf = min(i + 4, KQ - 1);
                wreg[j] = wp[(size_t)ipf * (OUT_SIZE / 4)];

                float4 xa = *(const float4*)(xb + i * XPAD);
                float4 xc = *(const float4*)(xb + i * XPAD + 4);
                unsigned long long x0 = pack2(xa.x);
                unsigned long long x1 = pack2(xa.y);
                unsigned long long x2 = pack2(xa.z);
                unsigned long long x3 = pack2(xa.w);
                unsigned long long x4 = pack2(xc.x);
                unsigned long long x5 = pack2(xc.y);
                unsigned long long x6 = pack2(xc.z);
                unsigned long long x7 = pack2(xc.w);
                fma2(acc[0][0], x0, w2.x); fma2(acc[0][1], x0, w2.y);
                fma2(acc[1][0], x1, w2.x); fma2(acc[1][1], x1, w2.y);
                fma2(acc[2][0], x2, w2.x); fma2(acc[2][1], x2, w2.y);
                fma2(acc[3][0], x3, w2.x); fma2(acc[3][1], x3, w2.y);
                fma2(acc[4][0], x4, w2.x); fma2(acc[4][1], x4, w2.y);
                fma2(acc[5][0], x5, w2.x); fma2(acc[5][1], x5, w2.y);
                fma2(acc[6][0], x6, w2.x); fma2(acc[6][1], x6, w2.y);
                fma2(acc[7][0], x7, w2.x); fma2(acc[7][1], x7, w2.y);
            }
        }

        // ---- epilogue: one red.global.add.v4 per valid sample ----
        const int obase = q * 4;
        #pragma unroll
        for (int s = 0; s < 8; s++) {
            int sid = sh * 8 + s;
            if (sid < cnt) {
                float* o = out + (size_t)rows_sm[sid] * OUT_SIZE + obase;
                float f0, f1, f2, f3;
                unpack2(acc[s][0], f0, f1);
                unpack2(acc[s][1], f2, f3);
                red4(o, f0, f1, f2, f3);
            }
        }
    }
}

// ---------------------------------------------------------------------------
extern "C" void kernel_launch(void* const* d_in, const int* in_sizes, int n_in,
                              void* d_out, int out_size) {
    const float* x   = nullptr;
    const void*  tsk = nullptr;
    const float* W   = nullptr;
    for (int i = 0; i < n_in; i++) {
        if (in_sizes[i] == N_SAMPLES * IN_SIZE)               x   = (const float*)d_in[i];
        else if (in_sizes[i] == N_SAMPLES)                    tsk = d_in[i];
        else if (in_sizes[i] == N_TASKS * IN_SIZE * OUT_SIZE) W   = (const float*)d_in[i];
    }
    float* out = (float*)d_out;

    cudaMemsetAsync(out, 0, (size_t)out_size * sizeof(float), 0);
    group_kernel<<<1, N_TASKS>>>(tsk);
    tsl_kernel<<<dim3(MAXCHUNK, NSPLIT), NTHR>>>(x, W, out);
}